// round 1
// baseline (speedup 1.0000x reference)
#include <cuda_runtime.h>
#include <cstdint>

#define BB 128
#define PP 8732
#define MM 16
#define TPB 256
#define THRESH 0.5f

__device__ float g_loc[BB];
__device__ float g_conf[BB];
__device__ int   g_npos[BB];

__device__ __forceinline__ float softplusf(float x) {
    // logaddexp(0, x) = max(x,0) + log1p(exp(-|x|))
    return fmaxf(x, 0.0f) + log1pf(expf(-fabsf(x)));
}

__global__ __launch_bounds__(TPB) void match_kernel(
    const float* __restrict__ locs,    // (B,P,4)
    const float* __restrict__ scores,  // (B,P,3)
    const float* __restrict__ boxes,   // (B,M,4) xyxy
    const int*   __restrict__ labels,  // (B,M)
    const float* __restrict__ priors)  // (P,4) cxcy
{
    __shared__ float sval[PP];            // phase1: ov_prior; phase3+: conf_neg
    __shared__ unsigned char sobj[PP];    // best object per prior
    __shared__ float bx1[MM], by1[MM], bx2[MM], by2[MM], barea[MM];
    __shared__ float bcx[MM], bcy[MM], bw[MM], bh[MM];
    __shared__ int   blab[MM];
    __shared__ unsigned long long bestkey[MM];
    __shared__ float w_f0[8], w_f1[8];
    __shared__ int   w_i0[8];
    __shared__ float s_conf, s_loc, s_sum;
    __shared__ int   s_np;
    __shared__ unsigned int s_cnt;

    const int b   = blockIdx.x;
    const int tid = threadIdx.x;
    const int warp = tid >> 5, lane = tid & 31;

    // ---- load boxes (xyxy + cxcywh + area) and labels ----
    if (tid < MM) {
        const float* bb = boxes + ((size_t)b * MM + tid) * 4;
        float x1 = bb[0], y1 = bb[1], x2 = bb[2], y2 = bb[3];
        bx1[tid] = x1; by1[tid] = y1; bx2[tid] = x2; by2[tid] = y2;
        barea[tid] = (x2 - x1) * (y2 - y1);
        bcx[tid] = (x1 + x2) * 0.5f;
        bcy[tid] = (y1 + y2) * 0.5f;
        bw[tid]  = x2 - x1;
        bh[tid]  = y2 - y1;
        blab[tid] = labels[b * MM + tid];
        bestkey[tid] = 0ull;
    }
    __syncthreads();

    // ---- Phase 1: IoU, per-prior max/argmax (first occurrence), per-object best prior ----
    unsigned long long lbest[MM];
#pragma unroll
    for (int m = 0; m < MM; m++) lbest[m] = 0ull;

    for (int p = tid; p < PP; p += TPB) {
        float4 pr = *(const float4*)(priors + (size_t)p * 4);
        float px1 = pr.x - pr.z * 0.5f, py1 = pr.y - pr.w * 0.5f;
        float px2 = pr.x + pr.z * 0.5f, py2 = pr.y + pr.w * 0.5f;
        float parea = pr.z * pr.w;
        float bov = -1.0f; int bm = 0;
#pragma unroll
        for (int m = 0; m < MM; m++) {
            float lx = fmaxf(bx1[m], px1), ly = fmaxf(by1[m], py1);
            float rx = fminf(bx2[m], px2), ry = fminf(by2[m], py2);
            float w = fmaxf(rx - lx, 0.0f), h = fmaxf(ry - ly, 0.0f);
            float inter = w * h;
            float iou = inter / (barea[m] + parea - inter);
            if (iou > bov) { bov = iou; bm = m; }   // strict > : first occurrence wins
            // per-object argmax with smallest-p tie-break: key = (iou_bits, ~p)
            unsigned long long key =
                ((unsigned long long)__float_as_uint(iou) << 32) |
                (unsigned)(0xFFFFFFFFu - (unsigned)p);
            lbest[m] = (key > lbest[m]) ? key : lbest[m];
        }
        sval[p] = bov;
        sobj[p] = (unsigned char)bm;
    }
#pragma unroll
    for (int m = 0; m < MM; m++) atomicMax(&bestkey[m], lbest[m]);
    __syncthreads();

    // ---- override: obj_prior[prior_obj[m]] = m ; ov_prior[...] = 1.0 (sequential, last wins) ----
    if (tid == 0) {
        for (int m = 0; m < MM; m++) {
            unsigned p = 0xFFFFFFFFu - (unsigned)(bestkey[m] & 0xFFFFFFFFull);
            sobj[p] = (unsigned char)m;
            sval[p] = 1.0f;
        }
    }
    __syncthreads();

    // ---- Phase 3: labels, BCE per prior, positive loc-loss, build conf_neg in sval ----
    float conf_pos = 0.0f, loc_sum = 0.0f;
    int npos = 0;
    for (int p = tid; p < PP; p += TPB) {
        float ov = sval[p];
        int obj = sobj[p];
        int lab = (ov < THRESH) ? 0 : blab[obj];
        const float* sc = scores + ((size_t)b * PP + p) * 3;
        float x0 = sc[0], x1 = sc[1], x2 = sc[2];
        float bce = softplusf(x0) + softplusf(x1) + softplusf(x2);
        // targets: lab 0 -> [1,0,0]; 1 -> [0,1,0]; 2 -> [0,0,1]; 3 -> [0,1,1]
        if (lab == 0) bce -= x0;
        if (lab == 1 || lab == 3) bce -= x1;
        if (lab == 2 || lab == 3) bce -= x2;
        if (lab > 0) {
            conf_pos += bce;
            npos++;
            sval[p] = 0.0f;
            float4 pr = *(const float4*)(priors + (size_t)p * 4);
            float gx = (bcx[obj] - pr.x) * 10.0f / pr.z;
            float gy = (bcy[obj] - pr.y) * 10.0f / pr.w;
            float gw = logf(bw[obj] / pr.z) * 5.0f;
            float gh = logf(bh[obj] / pr.w) * 5.0f;
            float4 pl = *(const float4*)(locs + ((size_t)b * PP + p) * 4);
            loc_sum += fabsf(pl.x - gx) + fabsf(pl.y - gy) +
                       fabsf(pl.z - gw) + fabsf(pl.w - gh);
        } else {
            sval[p] = bce;   // conf_neg (bce > 0 strictly)
        }
    }

    // ---- deterministic block reduce: conf_pos, loc_sum, npos ----
    for (int o = 16; o; o >>= 1) {
        conf_pos += __shfl_down_sync(0xFFFFFFFFu, conf_pos, o);
        loc_sum  += __shfl_down_sync(0xFFFFFFFFu, loc_sum, o);
        npos     += __shfl_down_sync(0xFFFFFFFFu, npos, o);
    }
    if (lane == 0) { w_f0[warp] = conf_pos; w_f1[warp] = loc_sum; w_i0[warp] = npos; }
    __syncthreads();
    if (tid == 0) {
        float c = 0.0f, l = 0.0f; int n = 0;
        for (int i = 0; i < 8; i++) { c += w_f0[i]; l += w_f1[i]; n += w_i0[i]; }
        s_conf = c; s_loc = l; s_np = n;
    }
    __syncthreads();

    const int npos_b = s_np;
    const unsigned K = 3u * (unsigned)npos_b;

    // ---- Phase 4: hard-negative mining = sum of top-K of sval (exact, via bit bisection) ----
    float hard = 0.0f;
    if (K > 0) {
        if (K >= (unsigned)PP) {
            // sum everything
            float s = 0.0f;
            for (int p = tid; p < PP; p += TPB) s += sval[p];
            for (int o = 16; o; o >>= 1) s += __shfl_down_sync(0xFFFFFFFFu, s, o);
            if (lane == 0) w_f0[warp] = s;
            __syncthreads();
            if (tid == 0) {
                float t = 0.0f;
                for (int i = 0; i < 8; i++) t += w_f0[i];
                s_sum = t;
            }
            __syncthreads();
            hard = s_sum;
        } else {
            // find K-th largest value's bit pattern (values >= 0 -> uint order == float order)
            unsigned lo = 0u, hi = 0x7F800000u;
            while (lo < hi) {
                unsigned mid = lo + ((hi - lo + 1u) >> 1);
                __syncthreads();
                if (tid == 0) s_cnt = 0u;
                __syncthreads();
                int c = 0;
                for (int p = tid; p < PP; p += TPB)
                    c += (__float_as_uint(sval[p]) >= mid);
                for (int o = 16; o; o >>= 1) c += __shfl_down_sync(0xFFFFFFFFu, c, o);
                if (lane == 0) atomicAdd(&s_cnt, (unsigned)c);
                __syncthreads();
                if (s_cnt >= K) lo = mid; else hi = mid - 1u;
            }
            const float thr = __uint_as_float(lo);
            __syncthreads();
            if (tid == 0) { s_cnt = 0u; }
            __syncthreads();
            int c = 0; float s = 0.0f;
            for (int p = tid; p < PP; p += TPB) {
                float v = sval[p];
                if (v > thr) { c++; s += v; }
            }
            for (int o = 16; o; o >>= 1) {
                c += __shfl_down_sync(0xFFFFFFFFu, c, o);
                s += __shfl_down_sync(0xFFFFFFFFu, s, o);
            }
            if (lane == 0) { w_f0[warp] = s; atomicAdd(&s_cnt, (unsigned)c); }
            __syncthreads();
            if (tid == 0) {
                float t = 0.0f;
                for (int i = 0; i < 8; i++) t += w_f0[i];
                s_sum = t + (float)((int)K - (int)s_cnt) * thr;
            }
            __syncthreads();
            hard = s_sum;
        }
    }

    if (tid == 0) {
        g_conf[b] = s_conf + hard;
        g_loc[b]  = s_loc;
        g_npos[b] = npos_b;
    }
}

__global__ void finalize_kernel(float* __restrict__ out, int out_size) {
    int t = threadIdx.x;
    if (t == 0) {
        float locs = 0.0f, confs = 0.0f;
        long long np = 0;
        for (int i = 0; i < BB; i++) {
            locs += g_loc[i];
            confs += g_conf[i];
            np += (long long)g_npos[i];
        }
        float npf = (float)np;
        float loc_loss  = (np > 0) ? locs / (4.0f * fmaxf(npf, 1.0f)) : 0.0f;
        float conf_loss = confs / (1e-10f + npf);
        float total = conf_loss + loc_loss;
        if (out_size > 0) out[0] = total;
        if (out_size > 1) out[1] = conf_loss;
        if (out_size > 2) out[2] = loc_loss;
    }
    for (int i = t; i < BB; i += blockDim.x)
        if (3 + i < out_size) out[3 + i] = (float)g_npos[i];
    for (int i = 3 + BB + t; i < out_size; i += blockDim.x)
        out[i] = 0.0f;
}

extern "C" void kernel_launch(void* const* d_in, const int* in_sizes, int n_in,
                              void* d_out, int out_size) {
    const float* locs   = (const float*)d_in[0];   // (128,8732,4) f32
    const float* scores = (const float*)d_in[1];   // (128,8732,3) f32
    const float* boxes  = (const float*)d_in[2];   // (128,16,4)   f32
    const int*   labels = (const int*)d_in[3];     // (128,16)     i32
    const float* priors = (const float*)d_in[4];   // (8732,4)     f32

    match_kernel<<<BB, TPB>>>(locs, scores, boxes, labels, priors);
    finalize_kernel<<<1, 256>>>((float*)d_out, out_size);
}

// round 2
// speedup vs baseline: 2.8146x; 2.8146x over previous
#include <cuda_runtime.h>
#include <cstdint>

#define BB 128
#define PP 8732
#define MM 16
#define TPB 512
#define THRESH 0.5f

__device__ float g_loc[BB];
__device__ float g_conf[BB];
__device__ int   g_npos[BB];

__device__ __forceinline__ float softplusf(float x) {
    // logaddexp(0,x) = max(x,0) + log1p(exp(-|x|))
    return fmaxf(x, 0.0f) + log1pf(__expf(-fabsf(x)));
}

__global__ __launch_bounds__(TPB, 1) void match_kernel(
    const float* __restrict__ locs,    // (B,P,4)
    const float* __restrict__ scores,  // (B,P,3)
    const float* __restrict__ boxes,   // (B,M,4) xyxy
    const int*   __restrict__ labels,  // (B,M)
    const float* __restrict__ priors)  // (P,4) cxcy
{
    __shared__ float sval[PP];            // phase1: ov_prior; phase3+: conf_neg
    __shared__ unsigned char sobj[PP];    // best object per prior
    __shared__ float4 sbox[MM];           // x1,y1,x2,y2
    __shared__ float sarea[MM];
    __shared__ float bcx[MM], bcy[MM], bwd[MM], bht[MM];
    __shared__ int   blab[MM];
    __shared__ unsigned long long bestkey[MM];
    __shared__ float w_f0[16], w_f1[16];
    __shared__ int   w_i0[16];
    __shared__ unsigned int cnt3[3];
    __shared__ float s_conf, s_loc, s_sum;
    __shared__ int   s_np;
    __shared__ unsigned int s_cnt;

    const int b    = blockIdx.x;
    const int tid  = threadIdx.x;
    const int warp = tid >> 5, lane = tid & 31;

    // ---- load boxes and labels ----
    if (tid < MM) {
        const float* bb = boxes + ((size_t)b * MM + tid) * 4;
        float x1 = bb[0], y1 = bb[1], x2 = bb[2], y2 = bb[3];
        sbox[tid] = make_float4(x1, y1, x2, y2);
        sarea[tid] = (x2 - x1) * (y2 - y1);
        bcx[tid] = (x1 + x2) * 0.5f;
        bcy[tid] = (y1 + y2) * 0.5f;
        bwd[tid] = x2 - x1;
        bht[tid] = y2 - y1;
        blab[tid] = labels[b * MM + tid];
        bestkey[tid] = 0ull;
    }
    if (tid < 3) cnt3[tid] = 0u;
    __syncthreads();

    // ---- Phase 1: IoU; per-prior argmax over m; per-object argmax over p ----
    float bi[MM];
    int   bp[MM];
#pragma unroll
    for (int m = 0; m < MM; m++) { bi[m] = -1.0f; bp[m] = 0; }

    for (int p = tid; p < PP; p += TPB) {
        float4 pr = *(const float4*)(priors + (size_t)p * 4);
        float px1 = pr.x - pr.z * 0.5f, py1 = pr.y - pr.w * 0.5f;
        float px2 = pr.x + pr.z * 0.5f, py2 = pr.y + pr.w * 0.5f;
        float parea = pr.z * pr.w;
        float bov = -1.0f; int bm = 0;
#pragma unroll
        for (int m = 0; m < MM; m++) {
            float4 bb = sbox[m];
            float lx = fmaxf(bb.x, px1), ly = fmaxf(bb.y, py1);
            float rx = fminf(bb.z, px2), ry = fminf(bb.w, py2);
            float w = fmaxf(rx - lx, 0.0f), h = fmaxf(ry - ly, 0.0f);
            float inter = w * h;
            float denom = (sarea[m] + parea) - inter;
            float iou = __fdividef(inter, denom);
            if (iou > bov) { bov = iou; bm = m; }    // first occurrence wins
            if (iou > bi[m]) { bi[m] = iou; bp[m] = p; }
        }
        sval[p] = bov;
        sobj[p] = (unsigned char)bm;
    }
    // warp-reduce per-object keys, then one atomic per warp
#pragma unroll
    for (int m = 0; m < MM; m++) {
        unsigned long long key =
            ((unsigned long long)__float_as_uint(bi[m]) << 32) |
            (unsigned)(0xFFFFFFFFu - (unsigned)bp[m]);
#pragma unroll
        for (int o = 16; o; o >>= 1) {
            unsigned long long other = __shfl_down_sync(0xFFFFFFFFu, key, o);
            key = (other > key) ? other : key;
        }
        if (lane == 0) atomicMax(&bestkey[m], key);
    }
    __syncthreads();

    // ---- override: obj_prior[prior_obj[m]] = m ; ov_prior = 1.0 (sequential last-wins) ----
    if (tid == 0) {
        for (int m = 0; m < MM; m++) {
            unsigned p = 0xFFFFFFFFu - (unsigned)(bestkey[m] & 0xFFFFFFFFull);
            sobj[p] = (unsigned char)m;
            sval[p] = 1.0f;
        }
    }
    __syncthreads();

    // ---- Phase 3: BCE per prior, positive loc-loss, conf_neg into sval ----
    float conf_pos = 0.0f, loc_sum = 0.0f;
    int npos = 0;
    for (int p = tid; p < PP; p += TPB) {
        float ov = sval[p];
        int obj = sobj[p];
        int lab = (ov < THRESH) ? 0 : blab[obj];
        const float* sc = scores + ((size_t)b * PP + p) * 3;
        float x0 = sc[0], x1 = sc[1], x2 = sc[2];
        float bce = softplusf(x0) + softplusf(x1) + softplusf(x2);
        if (lab == 0) bce -= x0;
        if (lab == 1 || lab == 3) bce -= x1;
        if (lab == 2 || lab == 3) bce -= x2;
        if (lab > 0) {
            conf_pos += bce;
            npos++;
            sval[p] = 0.0f;
            float4 pr = *(const float4*)(priors + (size_t)p * 4);
            float gx = (bcx[obj] - pr.x) * 10.0f * __fdividef(1.0f, pr.z);
            float gy = (bcy[obj] - pr.y) * 10.0f * __fdividef(1.0f, pr.w);
            float gw = __logf(__fdividef(bwd[obj], pr.z)) * 5.0f;
            float gh = __logf(__fdividef(bht[obj], pr.w)) * 5.0f;
            float4 pl = *(const float4*)(locs + ((size_t)b * PP + p) * 4);
            loc_sum += fabsf(pl.x - gx) + fabsf(pl.y - gy) +
                       fabsf(pl.z - gw) + fabsf(pl.w - gh);
        } else {
            sval[p] = bce;   // conf_neg (> 0)
        }
    }

    // ---- deterministic block reduce ----
#pragma unroll
    for (int o = 16; o; o >>= 1) {
        conf_pos += __shfl_down_sync(0xFFFFFFFFu, conf_pos, o);
        loc_sum  += __shfl_down_sync(0xFFFFFFFFu, loc_sum, o);
    }
    npos = __reduce_add_sync(0xFFFFFFFFu, npos);
    if (lane == 0) { w_f0[warp] = conf_pos; w_f1[warp] = loc_sum; w_i0[warp] = npos; }
    __syncthreads();
    if (tid == 0) {
        float c = 0.0f, l = 0.0f; int n = 0;
#pragma unroll
        for (int i = 0; i < 16; i++) { c += w_f0[i]; l += w_f1[i]; n += w_i0[i]; }
        s_conf = c; s_loc = l; s_np = n;
    }
    __syncthreads();

    const int npos_b = s_np;
    const unsigned K = 3u * (unsigned)npos_b;
    const unsigned int* su = (const unsigned int*)sval;

    // ---- Phase 4: sum of top-K of sval via bit bisection (1 barrier / round) ----
    float hard = 0.0f;
    if (K > 0) {
        if (K >= (unsigned)PP) {
            float s = 0.0f;
            for (int p = tid; p < PP; p += TPB) s += sval[p];
#pragma unroll
            for (int o = 16; o; o >>= 1) s += __shfl_down_sync(0xFFFFFFFFu, s, o);
            if (lane == 0) w_f0[warp] = s;
            __syncthreads();
            if (tid == 0) {
                float t = 0.0f;
#pragma unroll
                for (int i = 0; i < 16; i++) t += w_f0[i];
                s_sum = t;
            }
            __syncthreads();
            hard = s_sum;
        } else {
            unsigned lo = 0u, hi = 0x7F800000u;
            int r = 0;
            while (lo < hi) {
                unsigned mid = lo + ((hi - lo + 1u) >> 1);
                int c = 0;
                for (int p = tid; p < PP; p += TPB)
                    c += (su[p] >= mid);
                c = __reduce_add_sync(0xFFFFFFFFu, c);
                if (lane == 0) atomicAdd(&cnt3[r % 3], (unsigned)c);
                if (tid == 0) cnt3[(r + 1) % 3] = 0u;
                __syncthreads();
                unsigned total = cnt3[r % 3];
                if (total >= K) lo = mid; else hi = mid - 1u;
                r++;
            }
            const float thr = __uint_as_float(lo);
            if (tid == 0) s_cnt = 0u;
            __syncthreads();
            int c = 0; float s = 0.0f;
            for (int p = tid; p < PP; p += TPB) {
                float v = sval[p];
                if (v > thr) { c++; s += v; }
            }
#pragma unroll
            for (int o = 16; o; o >>= 1)
                s += __shfl_down_sync(0xFFFFFFFFu, s, o);
            c = __reduce_add_sync(0xFFFFFFFFu, c);
            if (lane == 0) { w_f0[warp] = s; atomicAdd(&s_cnt, (unsigned)c); }
            __syncthreads();
            if (tid == 0) {
                float t = 0.0f;
#pragma unroll
                for (int i = 0; i < 16; i++) t += w_f0[i];
                s_sum = t + (float)((int)K - (int)s_cnt) * thr;
            }
            __syncthreads();
            hard = s_sum;
        }
    }

    if (tid == 0) {
        g_conf[b] = s_conf + hard;
        g_loc[b]  = s_loc;
        g_npos[b] = npos_b;
    }
}

__global__ __launch_bounds__(BB) void finalize_kernel(float* __restrict__ out, int out_size) {
    __shared__ float wl[4], wc[4];
    __shared__ int   wn[4];
    const int t = threadIdx.x;          // 128 threads
    const int warp = t >> 5, lane = t & 31;

    float l = g_loc[t];
    float c = g_conf[t];
    int   n = g_npos[t];
#pragma unroll
    for (int o = 16; o; o >>= 1) {
        l += __shfl_down_sync(0xFFFFFFFFu, l, o);
        c += __shfl_down_sync(0xFFFFFFFFu, c, o);
    }
    n = __reduce_add_sync(0xFFFFFFFFu, n);
    if (lane == 0) { wl[warp] = l; wc[warp] = c; wn[warp] = n; }
    __syncthreads();
    if (t == 0) {
        float locs = 0.0f, confs = 0.0f;
        long long np = 0;
#pragma unroll
        for (int i = 0; i < 4; i++) { locs += wl[i]; confs += wc[i]; np += wn[i]; }
        float npf = (float)np;
        float loc_loss  = (np > 0) ? locs / (4.0f * fmaxf(npf, 1.0f)) : 0.0f;
        float conf_loss = confs / (1e-10f + npf);
        float total = conf_loss + loc_loss;
        if (out_size > 0) out[0] = total;
        if (out_size > 1) out[1] = conf_loss;
        if (out_size > 2) out[2] = loc_loss;
    }
    if (3 + t < out_size) out[3 + t] = (float)g_npos[t];
    for (int i = 3 + BB + t; i < out_size; i += BB)
        out[i] = 0.0f;
}

extern "C" void kernel_launch(void* const* d_in, const int* in_sizes, int n_in,
                              void* d_out, int out_size) {
    const float* locs   = (const float*)d_in[0];   // (128,8732,4) f32
    const float* scores = (const float*)d_in[1];   // (128,8732,3) f32
    const float* boxes  = (const float*)d_in[2];   // (128,16,4)   f32
    const int*   labels = (const int*)d_in[3];     // (128,16)     i32
    const float* priors = (const float*)d_in[4];   // (8732,4)     f32

    match_kernel<<<BB, TPB>>>(locs, scores, boxes, labels, priors);
    finalize_kernel<<<1, BB>>>((float*)d_out, out_size);
}

// round 3
// speedup vs baseline: 2.9400x; 1.0446x over previous
#include <cuda_runtime.h>
#include <cstdint>

#define BB 128
#define PP 8732
#define NG (PP/4)      // 2183
#define MM 16
#define TPB 512

__device__ float g_loc[BB];
__device__ float g_conf[BB];
__device__ int   g_npos[BB];
__device__ unsigned g_ctr = 0;

__global__ __launch_bounds__(TPB, 1) void multibox_kernel(
    const float* __restrict__ locs,    // (B,P,4)
    const float* __restrict__ scores,  // (B,P,3)
    const float* __restrict__ boxes,   // (B,M,4) xyxy
    const int*   __restrict__ labels,  // (B,M)
    const float* __restrict__ priors,  // (P,4) cxcy
    float* __restrict__ out, int out_size)
{
    __shared__ __align__(16) float sval[PP];      // conf_neg per prior
    __shared__ __align__(4)  unsigned char sobj[PP]; // obj index | 0x80 positive flag
    __shared__ float4 sbox[MM];
    __shared__ float bcx[MM], bcy[MM], bwd[MM], bht[MM];
    __shared__ int   blab[MM];
    __shared__ unsigned long long bestkey[MM];
    __shared__ float w_f0[16], w_f1[16];
    __shared__ int   w_i0[16];
    __shared__ unsigned cnt[9];                   // 3 rotating sets x 3 counters
    __shared__ float s_conf, s_loc, s_sum;
    __shared__ int   s_np, s_last;
    __shared__ unsigned s_cnt;

    const int b    = blockIdx.x;
    const int tid  = threadIdx.x;
    const int warp = tid >> 5, lane = tid & 31;

    // ---- load boxes/labels ----
    if (tid < MM) {
        float4 bb = *(const float4*)(boxes + ((size_t)b * MM + tid) * 4);
        sbox[tid] = bb;
        bcx[tid] = (bb.x + bb.z) * 0.5f;
        bcy[tid] = (bb.y + bb.w) * 0.5f;
        bwd[tid] = bb.z - bb.x;
        bht[tid] = bb.w - bb.y;
        blab[tid] = labels[b * MM + tid];
        bestkey[tid] = 0ull;
    }
    if (tid < 9) cnt[tid] = 0u;
    __syncthreads();

    // ---- Phase 1: IoU matching, division-free (cross-multiplied compares) ----
    float area[MM];
#pragma unroll
    for (int m = 0; m < MM; m++) {
        float4 bb = sbox[m];
        area[m] = (bb.z - bb.x) * (bb.w - bb.y);
    }
    float oint[MM], oden[MM]; int opri[MM];
#pragma unroll
    for (int m = 0; m < MM; m++) { oint[m] = 0.0f; oden[m] = 1.0f; opri[m] = 0; }

    for (int p = tid; p < PP; p += TPB) {
        float4 pr = *(const float4*)(priors + (size_t)p * 4);
        float hw = pr.z * 0.5f, hh = pr.w * 0.5f;
        float px1 = pr.x - hw, py1 = pr.y - hh, px2 = pr.x + hw, py2 = pr.y + hh;
        float parea = pr.z * pr.w;
        float bint = 0.0f, bden = 1.0f; int bm = 0;
#pragma unroll
        for (int m = 0; m < MM; m++) {
            float4 bb = sbox[m];
            float w = fminf(bb.z, px2) - fmaxf(bb.x, px1);
            float h = fminf(bb.w, py2) - fmaxf(bb.y, py1);
            w = fmaxf(w, 0.0f); h = fmaxf(h, 0.0f);
            float inter = w * h;
            float den = (area[m] + parea) - inter;
            if (inter * bden > bint * den) { bint = inter; bden = den; bm = m; }
            if (inter * oden[m] > oint[m] * den) { oint[m] = inter; oden[m] = den; opri[m] = p; }
        }
        bool pos = (2.0f * bint >= bden);   // iou >= 0.5 (exact rational)
        sobj[p] = (unsigned char)(bm | (pos ? 0x80 : 0));
    }

    // per-object argmax across threads: divide once per m, warp shfl reduce, 1 atomic/warp
#pragma unroll
    for (int m = 0; m < MM; m++) {
        float iou = __fdividef(oint[m], oden[m]);
        unsigned long long key =
            ((unsigned long long)__float_as_uint(iou) << 32) |
            (unsigned)(0xFFFFFFFFu - (unsigned)opri[m]);
#pragma unroll
        for (int o = 16; o; o >>= 1) {
            unsigned long long other = __shfl_down_sync(0xFFFFFFFFu, key, o);
            if (other > key) key = other;
        }
        if (lane == 0) atomicMax(&bestkey[m], key);
    }
    __syncthreads();

    // override: prior_obj[m] forced positive with object m (sequential, last wins)
    if (tid == 0) {
        for (int m = 0; m < MM; m++) {
            unsigned p = 0xFFFFFFFFu - (unsigned)(bestkey[m] & 0xFFFFFFFFull);
            sobj[p] = (unsigned char)(m | 0x80);
        }
    }
    __syncthreads();

    // ---- Phase 3: BCE + loc-loss, 4 priors/thread with float4 loads ----
    float conf_pos = 0.0f, loc_sum = 0.0f;
    int npos = 0;
    const float* srow = scores + (size_t)b * PP * 3;
    for (int g = tid; g < NG; g += TPB) {
        const float4* sp = (const float4*)srow + (size_t)g * 3;
        float4 s0 = sp[0], s1 = sp[1], s2 = sp[2];
        unsigned ob4 = ((const unsigned*)sobj)[g];
        float ch0[4] = { s0.x, s0.w, s1.z, s2.y };
        float ch1[4] = { s0.y, s1.x, s1.w, s2.z };
        float ch2[4] = { s0.z, s1.y, s2.x, s2.w };
        float v[4];
#pragma unroll
        for (int j = 0; j < 4; j++) {
            unsigned obf = (ob4 >> (8 * j)) & 0xFFu;
            int obj = (int)(obf & 0x7Fu);
            bool pos = (obf & 0x80u) != 0;
            float x0 = ch0[j], x1 = ch1[j], x2 = ch2[j];
            float bce = fmaxf(x0, 0.0f) + __logf(1.0f + __expf(-fabsf(x0)))
                      + fmaxf(x1, 0.0f) + __logf(1.0f + __expf(-fabsf(x1)))
                      + fmaxf(x2, 0.0f) + __logf(1.0f + __expf(-fabsf(x2)));
            int lab = pos ? blab[obj] : 0;
            if (lab == 0) bce -= x0;
            if (lab == 1 || lab == 3) bce -= x1;
            if (lab >= 2) bce -= x2;
            if (pos) {
                conf_pos += bce;
                npos++;
                v[j] = 0.0f;
                int p = 4 * g + j;
                float4 pr = *(const float4*)(priors + (size_t)p * 4);
                float gx = (bcx[obj] - pr.x) * 10.0f * __fdividef(1.0f, pr.z);
                float gy = (bcy[obj] - pr.y) * 10.0f * __fdividef(1.0f, pr.w);
                float gw = __logf(__fdividef(bwd[obj], pr.z)) * 5.0f;
                float gh = __logf(__fdividef(bht[obj], pr.w)) * 5.0f;
                float4 pl = *(const float4*)(locs + ((size_t)b * PP + p) * 4);
                loc_sum += fabsf(pl.x - gx) + fabsf(pl.y - gy) +
                           fabsf(pl.z - gw) + fabsf(pl.w - gh);
            } else {
                v[j] = bce;
            }
        }
        ((float4*)sval)[g] = make_float4(v[0], v[1], v[2], v[3]);
    }

    // ---- deterministic block reduce ----
#pragma unroll
    for (int o = 16; o; o >>= 1) {
        conf_pos += __shfl_down_sync(0xFFFFFFFFu, conf_pos, o);
        loc_sum  += __shfl_down_sync(0xFFFFFFFFu, loc_sum, o);
    }
    npos = __reduce_add_sync(0xFFFFFFFFu, npos);
    if (lane == 0) { w_f0[warp] = conf_pos; w_f1[warp] = loc_sum; w_i0[warp] = npos; }
    __syncthreads();
    if (tid == 0) {
        float c = 0.0f, l = 0.0f; int n = 0;
#pragma unroll
        for (int i = 0; i < 16; i++) { c += w_f0[i]; l += w_f1[i]; n += w_i0[i]; }
        s_conf = c; s_loc = l; s_np = n;
    }
    __syncthreads();

    const int npos_b = s_np;
    const unsigned K = 3u * (unsigned)npos_b;

    // ---- Phase 4: top-K sum via 4-way (2 bits/round) bit bisection ----
    float hard = 0.0f;
    if (K > 0) {
        unsigned lo = 0u, hi = 0x7F800000u;
        int r = 0;
        const float4* sv4 = (const float4*)sval;
        while (lo < hi) {
            unsigned span = hi - lo;
            unsigned c2v = lo + ((span + 1u) >> 1);          // in [lo+1, hi]
            unsigned c1v = lo + ((c2v - lo) >> 1);           // used if c2v-1 > lo
            unsigned c3v = c2v + ((hi - c2v + 1u) >> 1);     // used if hi > c2v
            int n1 = 0, n2 = 0, n3 = 0;
            for (int g = tid; g < NG; g += TPB) {
                float4 vv = sv4[g];
                unsigned u0 = __float_as_uint(vv.x), u1 = __float_as_uint(vv.y);
                unsigned u2 = __float_as_uint(vv.z), u3 = __float_as_uint(vv.w);
                n1 += (u0 >= c1v) + (u1 >= c1v) + (u2 >= c1v) + (u3 >= c1v);
                n2 += (u0 >= c2v) + (u1 >= c2v) + (u2 >= c2v) + (u3 >= c2v);
                n3 += (u0 >= c3v) + (u1 >= c3v) + (u2 >= c3v) + (u3 >= c3v);
            }
            n1 = __reduce_add_sync(0xFFFFFFFFu, n1);
            n2 = __reduce_add_sync(0xFFFFFFFFu, n2);
            n3 = __reduce_add_sync(0xFFFFFFFFu, n3);
            int s = (r % 3) * 3;
            if (lane == 0)      atomicAdd(&cnt[s + 0], (unsigned)n1);
            else if (lane == 1) atomicAdd(&cnt[s + 1], (unsigned)n2);
            else if (lane == 2) atomicAdd(&cnt[s + 2], (unsigned)n3);
            if (tid == 0) {
                int z = ((r + 1) % 3) * 3;
                cnt[z + 0] = 0u; cnt[z + 1] = 0u; cnt[z + 2] = 0u;
            }
            __syncthreads();
            unsigned N1 = cnt[s + 0], N2 = cnt[s + 1], N3 = cnt[s + 2];
            if (N2 >= K) {
                lo = c2v;
                if (hi > lo) { if (N3 >= K) lo = c3v; else hi = c3v - 1u; }
            } else {
                hi = c2v - 1u;
                if (hi > lo) { if (N1 >= K) lo = c1v; else hi = c1v - 1u; }
            }
            r++;
        }
        const float thr = __uint_as_float(lo);
        if (tid == 0) s_cnt = 0u;
        __syncthreads();
        int c = 0; float ssum = 0.0f;
        for (int g = tid; g < NG; g += TPB) {
            float4 vv = sv4[g];
            if (vv.x > thr) { c++; ssum += vv.x; }
            if (vv.y > thr) { c++; ssum += vv.y; }
            if (vv.z > thr) { c++; ssum += vv.z; }
            if (vv.w > thr) { c++; ssum += vv.w; }
        }
#pragma unroll
        for (int o = 16; o; o >>= 1)
            ssum += __shfl_down_sync(0xFFFFFFFFu, ssum, o);
        c = __reduce_add_sync(0xFFFFFFFFu, c);
        if (lane == 0) { w_f0[warp] = ssum; atomicAdd(&s_cnt, (unsigned)c); }
        __syncthreads();
        if (tid == 0) {
            float t = 0.0f;
#pragma unroll
            for (int i = 0; i < 16; i++) t += w_f0[i];
            s_sum = t + (float)((int)K - (int)s_cnt) * thr;
        }
        __syncthreads();
        hard = s_sum;
    }

    // ---- per-row results + last-CTA fused finalize ----
    if (tid == 0) {
        g_conf[b] = s_conf + hard;
        g_loc[b]  = s_loc;
        g_npos[b] = npos_b;
        __threadfence();
        unsigned v = atomicAdd(&g_ctr, 1u);
        s_last = (v == (unsigned)(BB - 1));
    }
    __syncthreads();

    if (s_last) {
        __threadfence();
        float l = 0.0f, c = 0.0f; int n = 0;
        if (tid < BB) { l = g_loc[tid]; c = g_conf[tid]; n = g_npos[tid]; }
#pragma unroll
        for (int o = 16; o; o >>= 1) {
            l += __shfl_down_sync(0xFFFFFFFFu, l, o);
            c += __shfl_down_sync(0xFFFFFFFFu, c, o);
        }
        n = __reduce_add_sync(0xFFFFFFFFu, n);
        if (lane == 0) { w_f0[warp] = l; w_f1[warp] = c; w_i0[warp] = n; }
        __syncthreads();
        if (tid == 0) {
            float locsum = 0.0f, confsum = 0.0f; long long np = 0;
#pragma unroll
            for (int i = 0; i < 16; i++) {
                locsum += w_f0[i]; confsum += w_f1[i]; np += w_i0[i];
            }
            float npf = (float)np;
            float loc_loss  = (np > 0) ? locsum / (4.0f * fmaxf(npf, 1.0f)) : 0.0f;
            float conf_loss = confsum / (1e-10f + npf);
            float total = conf_loss + loc_loss;
            if (out_size > 0) out[0] = total;
            if (out_size > 1) out[1] = conf_loss;
            if (out_size > 2) out[2] = loc_loss;
            g_ctr = 0u;    // reset for next graph replay
        }
        if (tid < BB && 3 + tid < out_size) out[3 + tid] = (float)g_npos[tid];
        for (int i = 3 + BB + tid; i < out_size; i += TPB) out[i] = 0.0f;
    }
}

extern "C" void kernel_launch(void* const* d_in, const int* in_sizes, int n_in,
                              void* d_out, int out_size) {
    const float* locs   = (const float*)d_in[0];   // (128,8732,4) f32
    const float* scores = (const float*)d_in[1];   // (128,8732,3) f32
    const float* boxes  = (const float*)d_in[2];   // (128,16,4)   f32
    const int*   labels = (const int*)d_in[3];     // (128,16)     i32
    const float* priors = (const float*)d_in[4];   // (8732,4)     f32

    multibox_kernel<<<BB, TPB>>>(locs, scores, boxes, labels, priors,
                                 (float*)d_out, out_size);
}